// round 6
// baseline (speedup 1.0000x reference)
#include <cuda_runtime.h>
#include <cstdint>

// Problem constants (fixed by reference)
#define Nn   4096
#define Ee   2048
#define Rr   4
#define F0   128
#define HDim 256
#define CAP  (4*1024*1024)   // nnz capacity; expected nnz ~1.68M (5% of 33.5M), 4M is >20 sigma safe

// ---------------- scratch (__device__ globals; no runtime allocation) ----------------
__device__ float g_rw[Rr];
__device__ float g_s[3*Rr];
__device__ float g_a [Rr*Nn];            // rw * dv
__device__ float g_de[Rr*Ee];            // de
__device__ int   g_cntE[Rr*Ee];
__device__ int   g_cntN[Rr*Nn];
__device__ int   g_eoff[Rr*Ee+1];
__device__ int   g_noff[Rr*Nn+1];
__device__ int   g_ecur[Rr*Ee];
__device__ int2  g_epack[CAP];           // (n, a[r,n] bits)  per edge-CSR slot
__device__ int2  g_npack[CAP];           // (e, de[r,e] bits) per node-CSR slot
__device__ float g_t  [(size_t)Rr*Ee*HDim];
__device__ float g_hn [(size_t)Rr*Nn*HDim];
__device__ float g_bufA[(size_t)Nn*HDim];
__device__ float g_bufB[(size_t)Nn*HDim];
__device__ float g_ws [Rr*HDim*HDim];    // per-layer s_r-scaled weights
__device__ float g_mu[HDim];
__device__ float g_rs[HDim];

// ---------------- tiny prep ----------------
__global__ void k_zero() {
    int i = blockIdx.x*256 + threadIdx.x;
    if (i < Rr*Ee) { g_cntE[i] = 0; g_ecur[i] = 0; }
}

__global__ void k_prep(const float* __restrict__ rel_attn, const float* __restrict__ imp) {
    if (threadIdx.x == 0) {
        float m = -1e30f;
        for (int r = 0; r < Rr; r++) m = fmaxf(m, rel_attn[r]);
        float e[Rr], s = 0.f;
        for (int r = 0; r < Rr; r++) { e[r] = expf(rel_attn[r] - m); s += e[r]; }
        for (int r = 0; r < Rr; r++) g_rw[r] = e[r] / s;
        for (int i = 0; i < 3*Rr; i++) g_s[i] = 1.f / (1.f + expf(-imp[i]));
    }
}

// ---------------- degrees ----------------
__global__ void k_degN(const float* __restrict__ H) {
    int rn = blockIdx.x;                       // r*N + n
    const float* row = H + (size_t)rn * Ee;
    int c = 0;
    for (int e = threadIdx.x; e < Ee; e += 256) c += (row[e] > 0.5f);
    __shared__ int sh[256];
    sh[threadIdx.x] = c; __syncthreads();
    for (int s = 128; s; s >>= 1) { if (threadIdx.x < s) sh[threadIdx.x] += sh[threadIdx.x+s]; __syncthreads(); }
    if (threadIdx.x == 0) {
        int tot = sh[0];
        g_cntN[rn] = tot;
        float rw = g_rw[rn / Nn];
        g_a[rn] = rw * rsqrtf(rw * (float)tot + 1e-8f);
    }
}

__global__ void k_degE(const float* __restrict__ H) {
    int r = blockIdx.x, ec = blockIdx.y, nc = blockIdx.z;
    int e = ec*256 + threadIdx.x;
    const float* base = H + ((size_t)r*Nn + (size_t)nc*256) * Ee + e;
    int c = 0;
    #pragma unroll 4
    for (int i = 0; i < 256; i++) c += (base[(size_t)i*Ee] > 0.5f);
    atomicAdd(&g_cntE[r*Ee + e], c);
}

__global__ void k_de() {
    int i = blockIdx.x*256 + threadIdx.x;
    if (i < Rr*Ee) {
        float rw = g_rw[i / Ee];
        g_de[i] = rsqrtf(rw * (float)g_cntE[i] + 1e-8f);
    }
}

// ---------------- single-block exclusive scan ----------------
__device__ void scan_body(const int* __restrict__ in, int* __restrict__ out, int L) {
    int tid = threadIdx.x;
    int chunk = L >> 10;                      // L is 8192 or 16384, 1024 threads
    int base = tid * chunk;
    int s = 0;
    for (int j = 0; j < chunk; j++) s += in[base+j];
    __shared__ int sh[1024];
    sh[tid] = s; __syncthreads();
    for (int off = 1; off < 1024; off <<= 1) {
        int v = (tid >= off) ? sh[tid-off] : 0;
        __syncthreads();
        sh[tid] += v;
        __syncthreads();
    }
    int run = (tid == 0) ? 0 : sh[tid-1];
    for (int j = 0; j < chunk; j++) { out[base+j] = run; run += in[base+j]; }
    if (tid == 1023) out[L] = run;
}
__global__ void k_scanE() { scan_body(g_cntE, g_eoff, Rr*Ee); }
__global__ void k_scanN() { scan_body(g_cntN, g_noff, Rr*Nn); }

// ---------------- CSR fill (both directions, one pass over H) ----------------
__global__ void k_fill(const float* __restrict__ H) {
    int rn = blockIdx.x;
    int r = rn / Nn, n = rn % Nn;
    __shared__ int sc;
    if (threadIdx.x == 0) sc = 0;
    __syncthreads();
    float arn = g_a[rn];
    int nbase = g_noff[rn];
    const float* row = H + (size_t)rn * Ee;
    for (int e = threadIdx.x; e < Ee; e += 256) {
        if (row[e] > 0.5f) {
            int re = r*Ee + e;
            int pe = g_eoff[re] + atomicAdd(&g_ecur[re], 1);
            if (pe < CAP) g_epack[pe] = make_int2(n, __float_as_int(arn));
            int pn = nbase + atomicAdd(&sc, 1);
            if (pn < CAP) g_npack[pn] = make_int2(e, __float_as_int(g_de[re]));
        }
    }
}

// ---------------- sparse stages ----------------
// t[r,e,:] = de[r,e] * sum_{n in e} a[r,n] * X[n,:]
template<int F>
__global__ void __launch_bounds__(128) k_spmm_t(const float* __restrict__ Xin) {
    int re = blockIdx.x;
    int i0 = g_eoff[re], i1 = g_eoff[re+1];
    int tid = threadIdx.x;
    if constexpr (F == 256) {
        const float2* X2 = reinterpret_cast<const float2*>(Xin);
        float ax = 0.f, ay = 0.f;
        #pragma unroll 4
        for (int i = i0; i < i1; i++) {
            int2 p = __ldg(&g_epack[i]);
            float c = __int_as_float(p.y);
            float2 x = __ldg(&X2[(size_t)p.x*128 + tid]);
            ax += c * x.x; ay += c * x.y;
        }
        float d = g_de[re];
        reinterpret_cast<float2*>(g_t)[(size_t)re*128 + tid] = make_float2(d*ax, d*ay);
    } else {
        float acc = 0.f;
        #pragma unroll 4
        for (int i = i0; i < i1; i++) {
            int2 p = __ldg(&g_epack[i]);
            acc += __int_as_float(p.y) * __ldg(&Xin[(size_t)p.x*128 + tid]);
        }
        g_t[(size_t)re*128 + tid] = g_de[re] * acc;
    }
}

// hn[r,n,:] = a[r,n] * sum_{e ni n} de[r,e] * t[r,e,:]
template<int F>
__global__ void __launch_bounds__(128) k_spmm_n() {
    int rn = blockIdx.x;
    int r = rn / Nn;
    int i0 = g_noff[rn], i1 = g_noff[rn+1];
    int tid = threadIdx.x;
    if constexpr (F == 256) {
        const float2* T2 = reinterpret_cast<const float2*>(g_t) + (size_t)r*Ee*128;
        float ax = 0.f, ay = 0.f;
        #pragma unroll 4
        for (int i = i0; i < i1; i++) {
            int2 p = __ldg(&g_npack[i]);
            float c = __int_as_float(p.y);
            float2 x = __ldg(&T2[(size_t)p.x*128 + tid]);
            ax += c * x.x; ay += c * x.y;
        }
        float a = g_a[rn];
        reinterpret_cast<float2*>(g_hn)[(size_t)rn*128 + tid] = make_float2(a*ax, a*ay);
    } else {
        const float* T1 = g_t + (size_t)r*Ee*128;
        float acc = 0.f;
        #pragma unroll 4
        for (int i = i0; i < i1; i++) {
            int2 p = __ldg(&g_npack[i]);
            acc += __int_as_float(p.y) * __ldg(&T1[(size_t)p.x*128 + tid]);
        }
        g_hn[(size_t)rn*128 + tid] = g_a[rn] * acc;
    }
}

// ---------------- scaled weight prep: ws[k][o] = s[layer][k/F] * W[k][o] ----------------
__global__ void k_ws(const float* __restrict__ W, int FN, int layer, int total) {
    int i = blockIdx.x*256 + threadIdx.x;
    if (i < total) g_ws[i] = W[i] * g_s[layer*Rr + i / FN];
}

// ---------------- fused over-r GEMM: C[n,o] = sum_k hn[k/F][n][k%F] * ws[k][o] (+bias, +resid) ----------------
__global__ void __launch_bounds__(256) k_gemm(int K, int F, int Nout,
                                              const float* __restrict__ bias,
                                              const float* __restrict__ resid,
                                              float* __restrict__ C) {
    __shared__ float As[16][68];
    __shared__ float Bs[16][64];
    int tid = threadIdx.x;
    int bm = blockIdx.x * 64, bn = blockIdx.y * 64;
    int tx = tid & 15, ty = tid >> 4;
    float acc[4][4];
    #pragma unroll
    for (int i = 0; i < 4; i++)
        #pragma unroll
        for (int j = 0; j < 4; j++) acc[i][j] = 0.f;

    int lm = tid >> 2, lk = (tid & 3) * 4;   // A tile: 64 rows x 16 k
    int bk = tid >> 4, bo = (tid & 15) * 4;  // B tile: 16 k x 64 o

    for (int k0 = 0; k0 < K; k0 += 16) {
        int r = k0 / F, fb = k0 % F;
        float4 va = *reinterpret_cast<const float4*>(
            g_hn + ((size_t)((size_t)r*Nn + bm + lm)) * F + fb + lk);
        As[lk+0][lm] = va.x; As[lk+1][lm] = va.y; As[lk+2][lm] = va.z; As[lk+3][lm] = va.w;
        float4 vb = *reinterpret_cast<const float4*>(g_ws + (size_t)(k0 + bk)*Nout + bn + bo);
        *reinterpret_cast<float4*>(&Bs[bk][bo]) = vb;
        __syncthreads();
        #pragma unroll
        for (int kk = 0; kk < 16; kk++) {
            float a0 = As[kk][ty*4+0], a1 = As[kk][ty*4+1], a2 = As[kk][ty*4+2], a3 = As[kk][ty*4+3];
            float b0 = Bs[kk][tx*4+0], b1 = Bs[kk][tx*4+1], b2 = Bs[kk][tx*4+2], b3 = Bs[kk][tx*4+3];
            acc[0][0] += a0*b0; acc[0][1] += a0*b1; acc[0][2] += a0*b2; acc[0][3] += a0*b3;
            acc[1][0] += a1*b0; acc[1][1] += a1*b1; acc[1][2] += a1*b2; acc[1][3] += a1*b3;
            acc[2][0] += a2*b0; acc[2][1] += a2*b1; acc[2][2] += a2*b2; acc[2][3] += a2*b3;
            acc[3][0] += a3*b0; acc[3][1] += a3*b1; acc[3][2] += a3*b2; acc[3][3] += a3*b3;
        }
        __syncthreads();
    }
    #pragma unroll
    for (int i = 0; i < 4; i++) {
        int n = bm + ty*4 + i;
        #pragma unroll
        for (int j = 0; j < 4; j++) {
            int o = bn + tx*4 + j;
            float v = acc[i][j] + bias[o];
            if (resid) v += resid[(size_t)n*Nout + o];
            C[(size_t)n*Nout + o] = v;
        }
    }
}

// ---------------- BatchNorm stats (over nodes, per feature) ----------------
__global__ void k_bnstat(const float* __restrict__ Xin) {
    int h = blockIdx.x;
    float s = 0.f, q = 0.f;
    for (int n = threadIdx.x; n < Nn; n += 256) {
        float v = Xin[(size_t)n*HDim + h];
        s += v; q += v*v;
    }
    __shared__ float sh[256], sh2[256];
    sh[threadIdx.x] = s; sh2[threadIdx.x] = q; __syncthreads();
    for (int st = 128; st; st >>= 1) {
        if (threadIdx.x < st) { sh[threadIdx.x] += sh[threadIdx.x+st]; sh2[threadIdx.x] += sh2[threadIdx.x+st]; }
        __syncthreads();
    }
    if (threadIdx.x == 0) {
        float mu = sh[0] / (float)Nn;
        float var = sh2[0] / (float)Nn - mu*mu;
        g_mu[h] = mu;
        g_rs[h] = rsqrtf(var + 1e-5f);
    }
}

// ---------------- BN apply + LayerNorm + ELU, fused per node ----------------
__global__ void k_bnln(const float* __restrict__ Xin,
                       const float* __restrict__ bg, const float* __restrict__ bb,
                       const float* __restrict__ lg, const float* __restrict__ lb,
                       float* __restrict__ Out) {
    int n = blockIdx.x, h = threadIdx.x;
    float v = (Xin[(size_t)n*HDim + h] - g_mu[h]) * g_rs[h] * bg[h] + bb[h];
    __shared__ float sh[256], sh2[256];
    sh[h] = v; sh2[h] = v*v; __syncthreads();
    for (int st = 128; st; st >>= 1) {
        if (h < st) { sh[h] += sh[h+st]; sh2[h] += sh2[h+st]; }
        __syncthreads();
    }
    float m = sh[0] / (float)HDim;
    float var = sh2[0] / (float)HDim - m*m;
    float u = (v - m) * rsqrtf(var + 1e-5f) * lg[h] + lb[h];
    Out[(size_t)n*HDim + h] = (u > 0.f) ? u : expm1f(u);
}

// ---------------- launch ----------------
extern "C" void kernel_launch(void* const* d_in, const int* in_sizes, int n_in,
                              void* d_out, int out_size) {
    const float* X   = (const float*)d_in[0];
    const float* H   = (const float*)d_in[1];
    const float* W1  = (const float*)d_in[2];
    const float* W2  = (const float*)d_in[3];
    const float* W3  = (const float*)d_in[4];
    const float* imp = (const float*)d_in[5];
    const float* b1  = (const float*)d_in[6];
    const float* b2  = (const float*)d_in[7];
    const float* b3  = (const float*)d_in[8];
    const float* bng = (const float*)d_in[9];
    const float* bnb = (const float*)d_in[10];
    const float* lng = (const float*)d_in[11];
    const float* lnb = (const float*)d_in[12];
    const float* ra  = (const float*)d_in[13];
    float* out = (float*)d_out;

    void *pA, *pB;
    cudaGetSymbolAddress(&pA, g_bufA);
    cudaGetSymbolAddress(&pB, g_bufB);
    float* bufA = (float*)pA;
    float* bufB = (float*)pB;

    // --- structure extraction (shared across all 3 conv layers) ---
    k_zero<<<(Rr*Ee + 255)/256, 256>>>();
    k_prep<<<1, 32>>>(ra, imp);
    k_degN<<<Rr*Nn, 256>>>(H);
    k_degE<<<dim3(Rr, Ee/256, Nn/256), 256>>>(H);
    k_de<<<(Rr*Ee + 255)/256, 256>>>();
    k_scanE<<<1, 1024>>>();
    k_scanN<<<1, 1024>>>();
    k_fill<<<Rr*Nn, 256>>>(H);

    // --- conv1: F=128 -> 256 ---
    k_spmm_t<128><<<Rr*Ee, 128>>>(X);
    k_spmm_n<128><<<Rr*Nn, 128>>>();
    k_ws<<<(Rr*128*256 + 255)/256, 256>>>(W1, 128*256, 0, Rr*128*256);
    k_gemm<<<dim3(Nn/64, 256/64), 256>>>(Rr*128, 128, 256, b1, nullptr, bufA);
    k_bnstat<<<HDim, 256>>>(bufA);
    k_bnln<<<Nn, HDim>>>(bufA, bng, bnb, lng, lnb, bufB);

    // --- conv2: 256 -> 256 ---
    k_spmm_t<256><<<Rr*Ee, 128>>>(bufB);
    k_spmm_n<256><<<Rr*Nn, 128>>>();
    k_ws<<<(Rr*256*256 + 255)/256, 256>>>(W2, 256*256, 1, Rr*256*256);
    k_gemm<<<dim3(Nn/64, 256/64), 256>>>(Rr*256, 256, 256, b2, nullptr, bufA);
    k_bnstat<<<HDim, 256>>>(bufA);
    k_bnln<<<Nn, HDim>>>(bufA, bng + HDim, bnb + HDim, lng + HDim, lnb + HDim, bufB);

    // --- conv3: 256 -> 128, + residual X ---
    k_spmm_t<256><<<Rr*Ee, 128>>>(bufB);
    k_spmm_n<256><<<Rr*Nn, 128>>>();
    k_ws<<<(Rr*256*128 + 255)/256, 256>>>(W3, 256*128, 2, Rr*256*128);
    k_gemm<<<dim3(Nn/64, 128/64), 256>>>(Rr*256, 256, 128, b3, X, out);
}

// round 9
// speedup vs baseline: 1.0484x; 1.0484x over previous
#include <cuda_runtime.h>
#include <cstdint>

// Problem constants (fixed by reference)
#define Nn   4096
#define Ee   2048
#define Rr   4
#define F0   128
#define HDim 256
#define CAP  (4*1024*1024)   // nnz capacity; expected nnz ~1.68M (5% of 33.5M), 4M is >20 sigma safe

// ---------------- scratch (__device__ globals; no runtime allocation) ----------------
__device__ float g_rw[Rr];
__device__ float g_s[3*Rr];
__device__ float g_a [Rr*Nn];            // rw * dv
__device__ float g_de[Rr*Ee];            // de
__device__ int   g_cntE[Rr*Ee];
__device__ int   g_cntN[Rr*Nn];
__device__ int   g_eoff[Rr*Ee+1];
__device__ int   g_noff[Rr*Nn+1];
__device__ int   g_ecur[Rr*Ee];
__device__ int2  g_epack[CAP];           // (n, a[r,n] bits)  per edge-CSR slot
__device__ int2  g_npack[CAP];           // (e, de[r,e] bits) per node-CSR slot
__device__ float g_t  [(size_t)Rr*Ee*HDim];
__device__ float g_hn [(size_t)Rr*Nn*HDim];
__device__ float g_bufA[(size_t)Nn*HDim];
__device__ float g_bufB[(size_t)Nn*HDim];
__device__ float g_ws [Rr*HDim*HDim];    // per-layer s_r-scaled weights
__device__ float g_mu[HDim];
__device__ float g_rs[HDim];

// ---------------- tiny prep ----------------
__global__ void k_zero() {
    int i = blockIdx.x*256 + threadIdx.x;
    if (i < Rr*Ee) { g_cntE[i] = 0; g_ecur[i] = 0; }
}

__global__ void k_prep(const float* __restrict__ rel_attn, const float* __restrict__ imp) {
    if (threadIdx.x == 0) {
        float m = -1e30f;
        for (int r = 0; r < Rr; r++) m = fmaxf(m, rel_attn[r]);
        float e[Rr], s = 0.f;
        for (int r = 0; r < Rr; r++) { e[r] = expf(rel_attn[r] - m); s += e[r]; }
        for (int r = 0; r < Rr; r++) g_rw[r] = e[r] / s;
        for (int i = 0; i < 3*Rr; i++) g_s[i] = 1.f / (1.f + expf(-imp[i]));
    }
}

// ---------------- degrees ----------------
__global__ void k_degN(const float* __restrict__ H) {
    int rn = blockIdx.x;                       // r*N + n
    const float* row = H + (size_t)rn * Ee;
    int c = 0;
    for (int e = threadIdx.x; e < Ee; e += 256) c += (row[e] > 0.5f);
    __shared__ int sh[256];
    sh[threadIdx.x] = c; __syncthreads();
    for (int s = 128; s; s >>= 1) { if (threadIdx.x < s) sh[threadIdx.x] += sh[threadIdx.x+s]; __syncthreads(); }
    if (threadIdx.x == 0) {
        int tot = sh[0];
        g_cntN[rn] = tot;
        float rw = g_rw[rn / Nn];
        g_a[rn] = rw * rsqrtf(rw * (float)tot + 1e-8f);
    }
}

__global__ void k_degE(const float* __restrict__ H) {
    int r = blockIdx.x, ec = blockIdx.y, nc = blockIdx.z;
    int e = ec*256 + threadIdx.x;
    const float* base = H + ((size_t)r*Nn + (size_t)nc*256) * Ee + e;
    int c = 0;
    #pragma unroll 4
    for (int i = 0; i < 256; i++) c += (base[(size_t)i*Ee] > 0.5f);
    atomicAdd(&g_cntE[r*Ee + e], c);
}

__global__ void k_de() {
    int i = blockIdx.x*256 + threadIdx.x;
    if (i < Rr*Ee) {
        float rw = g_rw[i / Ee];
        g_de[i] = rsqrtf(rw * (float)g_cntE[i] + 1e-8f);
    }
}

// ---------------- single-block exclusive scan ----------------
__device__ void scan_body(const int* __restrict__ in, int* __restrict__ out, int L) {
    int tid = threadIdx.x;
    int chunk = L >> 10;                      // L is 8192 or 16384, 1024 threads
    int base = tid * chunk;
    int s = 0;
    for (int j = 0; j < chunk; j++) s += in[base+j];
    __shared__ int sh[1024];
    sh[tid] = s; __syncthreads();
    for (int off = 1; off < 1024; off <<= 1) {
        int v = (tid >= off) ? sh[tid-off] : 0;
        __syncthreads();
        sh[tid] += v;
        __syncthreads();
    }
    int run = (tid == 0) ? 0 : sh[tid-1];
    for (int j = 0; j < chunk; j++) { out[base+j] = run; run += in[base+j]; }
    if (tid == 1023) out[L] = run;
}
__global__ void k_scanE() { scan_body(g_cntE, g_eoff, Rr*Ee); }
__global__ void k_scanN() { scan_body(g_cntN, g_noff, Rr*Nn); }

// ---------------- CSR fill (both directions, one pass over H) ----------------
__global__ void k_fill(const float* __restrict__ H) {
    int rn = blockIdx.x;
    int r = rn / Nn, n = rn % Nn;
    __shared__ int sc;
    if (threadIdx.x == 0) sc = 0;
    __syncthreads();
    float arn = g_a[rn];
    int nbase = g_noff[rn];
    const float* row = H + (size_t)rn * Ee;
    for (int e = threadIdx.x; e < Ee; e += 256) {
        if (row[e] > 0.5f) {
            int re = r*Ee + e;
            int pe = g_eoff[re] + atomicAdd(&g_ecur[re], 1);
            if (pe < CAP) g_epack[pe] = make_int2(n, __float_as_int(arn));
            int pn = nbase + atomicAdd(&sc, 1);
            if (pn < CAP) g_npack[pn] = make_int2(e, __float_as_int(g_de[re]));
        }
    }
}

// ---------------- sparse stages ----------------
// t[r,e,:] = de[r,e] * sum_{n in e} a[r,n] * X[n,:]
template<int F>
__global__ void __launch_bounds__(128) k_spmm_t(const float* __restrict__ Xin) {
    int re = blockIdx.x;
    int i0 = g_eoff[re], i1 = g_eoff[re+1];
    int tid = threadIdx.x;
    if constexpr (F == 256) {
        const float2* X2 = reinterpret_cast<const float2*>(Xin);
        float ax = 0.f, ay = 0.f;
        #pragma unroll 4
        for (int i = i0; i < i1; i++) {
            int2 p = __ldg(&g_epack[i]);
            float c = __int_as_float(p.y);
            float2 x = __ldg(&X2[(size_t)p.x*128 + tid]);
            ax += c * x.x; ay += c * x.y;
        }
        float d = g_de[re];
        reinterpret_cast<float2*>(g_t)[(size_t)re*128 + tid] = make_float2(d*ax, d*ay);
    } else {
        float acc = 0.f;
        #pragma unroll 4
        for (int i = i0; i < i1; i++) {
            int2 p = __ldg(&g_epack[i]);
            acc += __int_as_float(p.y) * __ldg(&Xin[(size_t)p.x*128 + tid]);
        }
        g_t[(size_t)re*128 + tid] = g_de[re] * acc;
    }
}

// hn[r,n,:] = a[r,n] * sum_{e ni n} de[r,e] * t[r,e,:]
template<int F>
__global__ void __launch_bounds__(128) k_spmm_n() {
    int rn = blockIdx.x;
    int r = rn / Nn;
    int i0 = g_noff[rn], i1 = g_noff[rn+1];
    int tid = threadIdx.x;
    if constexpr (F == 256) {
        const float2* T2 = reinterpret_cast<const float2*>(g_t) + (size_t)r*Ee*128;
        float ax = 0.f, ay = 0.f;
        #pragma unroll 4
        for (int i = i0; i < i1; i++) {
            int2 p = __ldg(&g_npack[i]);
            float c = __int_as_float(p.y);
            float2 x = __ldg(&T2[(size_t)p.x*128 + tid]);
            ax += c * x.x; ay += c * x.y;
        }
        float a = g_a[rn];
        reinterpret_cast<float2*>(g_hn)[(size_t)rn*128 + tid] = make_float2(a*ax, a*ay);
    } else {
        const float* T1 = g_t + (size_t)r*Ee*128;
        float acc = 0.f;
        #pragma unroll 4
        for (int i = i0; i < i1; i++) {
            int2 p = __ldg(&g_npack[i]);
            acc += __int_as_float(p.y) * __ldg(&T1[(size_t)p.x*128 + tid]);
        }
        g_hn[(size_t)rn*128 + tid] = g_a[rn] * acc;
    }
}

// ---------------- scaled weight prep: ws[k][o] = s[layer][k/F] * W[k][o] ----------------
__global__ void k_ws(const float* __restrict__ W, int FN, int layer, int total) {
    int i = blockIdx.x*256 + threadIdx.x;
    if (i < total) g_ws[i] = W[i] * g_s[layer*Rr + i / FN];
}

// ---------------- fused over-r GEMM: C[n,o] = sum_k hn[k/F][n][k%F] * ws[k][o] (+bias, +resid) ----------------
__global__ void __launch_bounds__(256) k_gemm(int K, int F, int Nout,
                                              const float* __restrict__ bias,
                                              const float* __restrict__ resid,
                                              float* __restrict__ C) {
    __shared__ float As[16][68];
    __shared__ float Bs[16][64];
    int tid = threadIdx.x;
    int bm = blockIdx.x * 64, bn = blockIdx.y * 64;
    int tx = tid & 15, ty = tid >> 4;
    float acc[4][4];
    #pragma unroll
    for (int i = 0; i < 4; i++)
        #pragma unroll
        for (int j = 0; j < 4; j++) acc[i][j] = 0.f;

    int lm = tid >> 2, lk = (tid & 3) * 4;   // A tile: 64 rows x 16 k
    int bk = tid >> 4, bo = (tid & 15) * 4;  // B tile: 16 k x 64 o

    for (int k0 = 0; k0 < K; k0 += 16) {
        int r = k0 / F, fb = k0 % F;
        float4 va = *reinterpret_cast<const float4*>(
            g_hn + ((size_t)((size_t)r*Nn + bm + lm)) * F + fb + lk);
        As[lk+0][lm] = va.x; As[lk+1][lm] = va.y; As[lk+2][lm] = va.z; As[lk+3][lm] = va.w;
        float4 vb = *reinterpret_cast<const float4*>(g_ws + (size_t)(k0 + bk)*Nout + bn + bo);
        *reinterpret_cast<float4*>(&Bs[bk][bo]) = vb;
        __syncthreads();
        #pragma unroll
        for (int kk = 0; kk < 16; kk++) {
            float a0 = As[kk][ty*4+0], a1 = As[kk][ty*4+1], a2 = As[kk][ty*4+2], a3 = As[kk][ty*4+3];
            float b0 = Bs[kk][tx*4+0], b1 = Bs[kk][tx*4+1], b2 = Bs[kk][tx*4+2], b3 = Bs[kk][tx*4+3];
            acc[0][0] += a0*b0; acc[0][1] += a0*b1; acc[0][2] += a0*b2; acc[0][3] += a0*b3;
            acc[1][0] += a1*b0; acc[1][1] += a1*b1; acc[1][2] += a1*b2; acc[1][3] += a1*b3;
            acc[2][0] += a2*b0; acc[2][1] += a2*b1; acc[2][2] += a2*b2; acc[2][3] += a2*b3;
            acc[3][0] += a3*b0; acc[3][1] += a3*b1; acc[3][2] += a3*b2; acc[3][3] += a3*b3;
        }
        __syncthreads();
    }
    #pragma unroll
    for (int i = 0; i < 4; i++) {
        int n = bm + ty*4 + i;
        #pragma unroll
        for (int j = 0; j < 4; j++) {
            int o = bn + tx*4 + j;
            float v = acc[i][j] + bias[o];
            if (resid) v += resid[(size_t)n*Nout + o];
            C[(size_t)n*Nout + o] = v;
        }
    }
}

// ---------------- BatchNorm stats (over nodes, per feature) ----------------
__global__ void k_bnstat(const float* __restrict__ Xin) {
    int h = blockIdx.x;
    float s = 0.f, q = 0.f;
    for (int n = threadIdx.x; n < Nn; n += 256) {
        float v = Xin[(size_t)n*HDim + h];
        s += v; q += v*v;
    }
    __shared__ float sh[256], sh2[256];
    sh[threadIdx.x] = s; sh2[threadIdx.x] = q; __syncthreads();
    for (int st = 128; st; st >>= 1) {
        if (threadIdx.x < st) { sh[threadIdx.x] += sh[threadIdx.x+st]; sh2[threadIdx.x] += sh2[threadIdx.x+st]; }
        __syncthreads();
    }
    if (threadIdx.x == 0) {
        float mu = sh[0] / (float)Nn;
        float var = sh2[0] / (float)Nn - mu*mu;
        g_mu[h] = mu;
        g_rs[h] = rsqrtf(var + 1e-5f);
    }
}

// ---------------- BN apply + LayerNorm + ELU, fused per node ----------------
__global__ void k_bnln(const float* __restrict__ Xin,
                       const float* __restrict__ bg, const float* __restrict__ bb,
                       const float* __restrict__ lg, const float* __restrict__ lb,
                       float* __restrict__ Out) {
    int n = blockIdx.x, h = threadIdx.x;
    float v = (Xin[(size_t)n*HDim + h] - g_mu[h]) * g_rs[h] * bg[h] + bb[h];
    __shared__ float sh[256], sh2[256];
    sh[h] = v; sh2[h] = v*v; __syncthreads();
    for (int st = 128; st; st >>= 1) {
        if (h < st) { sh[h] += sh[h+st]; sh2[h] += sh2[h+st]; }
        __syncthreads();
    }
    float m = sh[0] / (float)HDim;
    float var = sh2[0] / (float)HDim - m*m;
    float u = (v - m) * rsqrtf(var + 1e-5f) * lg[h] + lb[h];
    Out[(size_t)n*HDim + h] = (u > 0.f) ? u : expm1f(u);
}

// ---------------- launch ----------------
extern "C" void kernel_launch(void* const* d_in, const int* in_sizes, int n_in,
                              void* d_out, int out_size) {
    const float* X   = (const float*)d_in[0];
    const float* H   = (const float*)d_in[1];
    const float* W1  = (const float*)d_in[2];
    const float* W2  = (const float*)d_in[3];
    const float* W3  = (const float*)d_in[4];
    const float* imp = (const float*)d_in[5];
    const float* b1  = (const float*)d_in[6];
    const float* b2  = (const float*)d_in[7];
    const float* b3  = (const float*)d_in[8];
    const float* bng = (const float*)d_in[9];
    const float* bnb = (const float*)d_in[10];
    const float* lng = (const float*)d_in[11];
    const float* lnb = (const float*)d_in[12];
    const float* ra  = (const float*)d_in[13];
    float* out = (float*)d_out;

    void *pA, *pB;
    cudaGetSymbolAddress(&pA, g_bufA);
    cudaGetSymbolAddress(&pB, g_bufB);
    float* bufA = (float*)pA;
    float* bufB = (float*)pB;

    // --- structure extraction (shared across all 3 conv layers) ---
    k_zero<<<(Rr*Ee + 255)/256, 256>>>();
    k_prep<<<1, 32>>>(ra, imp);
    k_degN<<<Rr*Nn, 256>>>(H);
    k_degE<<<dim3(Rr, Ee/256, Nn/256), 256>>>(H);
    k_de<<<(Rr*Ee + 255)/256, 256>>>();
    k_scanE<<<1, 1024>>>();
    k_scanN<<<1, 1024>>>();
    k_fill<<<Rr*Nn, 256>>>(H);

    // --- conv1: F=128 -> 256 ---
    k_spmm_t<128><<<Rr*Ee, 128>>>(X);
    k_spmm_n<128><<<Rr*Nn, 128>>>();
    k_ws<<<(Rr*128*256 + 255)/256, 256>>>(W1, 128*256, 0, Rr*128*256);
    k_gemm<<<dim3(Nn/64, 256/64), 256>>>(Rr*128, 128, 256, b1, nullptr, bufA);
    k_bnstat<<<HDim, 256>>>(bufA);
    k_bnln<<<Nn, HDim>>>(bufA, bng, bnb, lng, lnb, bufB);

    // --- conv2: 256 -> 256 ---
    k_spmm_t<256><<<Rr*Ee, 128>>>(bufB);
    k_spmm_n<256><<<Rr*Nn, 128>>>();
    k_ws<<<(Rr*256*256 + 255)/256, 256>>>(W2, 256*256, 1, Rr*256*256);
    k_gemm<<<dim3(Nn/64, 256/64), 256>>>(Rr*256, 256, 256, b2, nullptr, bufA);
    k_bnstat<<<HDim, 256>>>(bufA);
    k_bnln<<<Nn, HDim>>>(bufA, bng + HDim, bnb + HDim, lng + HDim, lnb + HDim, bufB);

    // --- conv3: 256 -> 128, + residual X ---
    k_spmm_t<256><<<Rr*Ee, 128>>>(bufB);
    k_spmm_n<256><<<Rr*Nn, 128>>>();
    k_ws<<<(Rr*256*128 + 255)/256, 256>>>(W3, 256*128, 2, Rr*256*128);
    k_gemm<<<dim3(Nn/64, 128/64), 256>>>(Rr*256, 256, 128, b3, X, out);
}

// round 11
// speedup vs baseline: 1.2156x; 1.1595x over previous
#include <cuda_runtime.h>
#include <cstdint>

#define Nn   4096
#define Ee   2048
#define Rr   4
#define HDim 256
#define CAP  (4*1024*1024)

// ---------------- scratch ----------------
__device__ float g_rw[Rr];
__device__ float g_s[3*Rr];
__device__ float g_a [Rr*Nn];
__device__ float g_de[Rr*Ee];
__device__ int   g_cntE[Rr*Ee];
__device__ int   g_cntN[Rr*Nn];
__device__ int   g_eoff[Rr*Ee+1];
__device__ int   g_noff[Rr*Nn+1];
__device__ int   g_ecur[Rr*Ee];
__device__ unsigned g_bm[Rr*Nn*64];          // H bitmask, 4MB
__device__ int2  g_epack[CAP];
__device__ int2  g_npack[CAP];
__device__ float g_t  [(size_t)Rr*Ee*HDim];
__device__ float g_hn [(size_t)Rr*Nn*HDim];
__device__ float g_y  [(size_t)Rr*Nn*128];   // layer-3 pre-multiplied h*W3
__device__ float g_bufA[(size_t)Nn*HDim];
__device__ float g_bufB[(size_t)Nn*HDim];
__device__ float g_ws [Rr*HDim*HDim];
__device__ float g_mu[HDim];
__device__ float g_rs[HDim];

// ---------------- prep ----------------
__global__ void k_zero() {
    int i = blockIdx.x*256 + threadIdx.x;
    if (i < Rr*Ee) { g_cntE[i] = 0; g_ecur[i] = 0; }
}

__global__ void k_prep(const float* __restrict__ rel_attn, const float* __restrict__ imp) {
    if (threadIdx.x == 0) {
        float m = -1e30f;
        for (int r = 0; r < Rr; r++) m = fmaxf(m, rel_attn[r]);
        float e[Rr], s = 0.f;
        for (int r = 0; r < Rr; r++) { e[r] = expf(rel_attn[r] - m); s += e[r]; }
        for (int r = 0; r < Rr; r++) g_rw[r] = e[r] / s;
        for (int i = 0; i < 3*Rr; i++) g_s[i] = 1.f / (1.f + expf(-imp[i]));
    }
}

// ---------------- single pass over H: bitmask + node degree + a ----------------
__global__ void k_pass1(const float* __restrict__ H) {
    int rn = blockIdx.x*8 + (threadIdx.x >> 5);
    int lane = threadIdx.x & 31;
    const float* row = H + (size_t)rn * Ee;
    int c = 0;
    #pragma unroll 8
    for (int w = 0; w < 64; w++) {
        bool pred = row[w*32 + lane] > 0.5f;
        unsigned b = __ballot_sync(0xFFFFFFFFu, pred);
        if (lane == 0) g_bm[rn*64 + w] = b;
        c += pred;
    }
    #pragma unroll
    for (int s = 16; s; s >>= 1) c += __shfl_xor_sync(0xFFFFFFFFu, c, s);
    if (lane == 0) {
        g_cntN[rn] = c;
        float rw = g_rw[rn >> 12];
        g_a[rn] = rw * rsqrtf(rw * (float)c + 1e-8f);
    }
}

// ---------------- edge degrees from bitmask (no atomics) ----------------
__global__ void k_degE2() {            // grid Rr*64, block 256
    int r = blockIdx.x >> 6, w = blockIdx.x & 63;
    int tid = threadIdx.x, lane = tid & 31, wid = tid >> 5;
    int c[32];
    #pragma unroll
    for (int b = 0; b < 32; b++) c[b] = 0;
    for (int n = tid; n < Nn; n += 256) {
        unsigned v = g_bm[(r*Nn + n)*64 + w];
        #pragma unroll
        for (int b = 0; b < 32; b++) c[b] += (v >> b) & 1;
    }
    __shared__ int sh[8][32];
    #pragma unroll
    for (int b = 0; b < 32; b++) {
        int v = c[b];
        #pragma unroll
        for (int s = 16; s; s >>= 1) v += __shfl_xor_sync(0xFFFFFFFFu, v, s);
        if (lane == 0) sh[wid][b] = v;
    }
    __syncthreads();
    if (tid < 32) {
        int t = 0;
        #pragma unroll
        for (int i = 0; i < 8; i++) t += sh[i][tid];
        g_cntE[(r << 11) + w*32 + tid] = t;
    }
}

__global__ void k_de() {
    int i = blockIdx.x*256 + threadIdx.x;
    if (i < Rr*Ee) {
        float rw = g_rw[i >> 11];
        g_de[i] = rsqrtf(rw * (float)g_cntE[i] + 1e-8f);
    }
}

// ---------------- single-block exclusive scan ----------------
__device__ void scan_body(const int* __restrict__ in, int* __restrict__ out, int L) {
    int tid = threadIdx.x;
    int chunk = L >> 10;
    int base = tid * chunk;
    int s = 0;
    for (int j = 0; j < chunk; j++) s += in[base+j];
    __shared__ int sh[1024];
    sh[tid] = s; __syncthreads();
    for (int off = 1; off < 1024; off <<= 1) {
        int v = (tid >= off) ? sh[tid-off] : 0;
        __syncthreads();
        sh[tid] += v;
        __syncthreads();
    }
    int run = (tid == 0) ? 0 : sh[tid-1];
    for (int j = 0; j < chunk; j++) { out[base+j] = run; run += in[base+j]; }
    if (tid == 1023) out[L] = run;
}
__global__ void k_scanE() { scan_body(g_cntE, g_eoff, Rr*Ee); }
__global__ void k_scanN() { scan_body(g_cntN, g_noff, Rr*Nn); }

// ---------------- CSR fill from bitmask ----------------
__global__ void k_fillb() {
    int rn = blockIdx.x;
    int r = rn >> 12, n = rn & 4095;
    __shared__ int sc;
    if (threadIdx.x == 0) sc = 0;
    __syncthreads();
    float arn = g_a[rn];
    int nbase = g_noff[rn];
    for (int e = threadIdx.x; e < Ee; e += 256) {
        if ((g_bm[rn*64 + (e >> 5)] >> (e & 31)) & 1u) {
            int re = (r << 11) + e;
            int pe = g_eoff[re] + atomicAdd(&g_ecur[re], 1);
            if (pe < CAP) g_epack[pe] = make_int2(n, __float_as_int(arn));
            int pn = nbase + atomicAdd(&sc, 1);
            if (pn < CAP) g_npack[pn] = make_int2(e, __float_as_int(g_de[re]));
        }
    }
}

// ---------------- sparse stages (proven inner loops; added per-r input base) ----------------
template<int F>
__global__ void __launch_bounds__(128) k_spmm_t(const float* __restrict__ Xin, int rstride) {
    int re = blockIdx.x;
    int i0 = g_eoff[re], i1 = g_eoff[re+1];
    int tid = threadIdx.x;
    const float* Xp = Xin + (size_t)(re >> 11) * rstride;
    if constexpr (F == 256) {
        const float2* X2 = reinterpret_cast<const float2*>(Xp);
        float ax = 0.f, ay = 0.f;
        #pragma unroll 4
        for (int i = i0; i < i1; i++) {
            int2 p = __ldg(&g_epack[i]);
            float c = __int_as_float(p.y);
            float2 x = __ldg(&X2[(size_t)p.x*128 + tid]);
            ax += c * x.x; ay += c * x.y;
        }
        float d = g_de[re];
        reinterpret_cast<float2*>(g_t)[(size_t)re*128 + tid] = make_float2(d*ax, d*ay);
    } else {
        float acc = 0.f;
        #pragma unroll 4
        for (int i = i0; i < i1; i++) {
            int2 p = __ldg(&g_epack[i]);
            acc += __int_as_float(p.y) * __ldg(&Xp[(size_t)p.x*128 + tid]);
        }
        g_t[(size_t)re*128 + tid] = g_de[re] * acc;
    }
}

template<int F>
__global__ void __launch_bounds__(128) k_spmm_n() {
    int rn = blockIdx.x;
    int r = rn >> 12;
    int i0 = g_noff[rn], i1 = g_noff[rn+1];
    int tid = threadIdx.x;
    if constexpr (F == 256) {
        const float2* T2 = reinterpret_cast<const float2*>(g_t) + (size_t)r*Ee*128;
        float ax = 0.f, ay = 0.f;
        #pragma unroll 4
        for (int i = i0; i < i1; i++) {
            int2 p = __ldg(&g_npack[i]);
            float c = __int_as_float(p.y);
            float2 x = __ldg(&T2[(size_t)p.x*128 + tid]);
            ax += c * x.x; ay += c * x.y;
        }
        float a = g_a[rn];
        reinterpret_cast<float2*>(g_hn)[(size_t)rn*128 + tid] = make_float2(a*ax, a*ay);
    } else {
        const float* T1 = g_t + (size_t)r*Ee*128;   // F=128 rows
        float acc = 0.f;
        #pragma unroll 4
        for (int i = i0; i < i1; i++) {
            int2 p = __ldg(&g_npack[i]);
            acc += __int_as_float(p.y) * __ldg(&T1[(size_t)p.x*128 + tid]);
        }
        g_hn[(size_t)rn*128 + tid] = g_a[rn] * acc;
    }
}

// ---------------- scaled weights ----------------
__global__ void k_ws(const float* __restrict__ W, int FN, int layer, int total) {
    int i = blockIdx.x*256 + threadIdx.x;
    if (i < total) g_ws[i] = W[i] * g_s[layer*Rr + i / FN];
}

// ---------------- GEMM: 128x64 tile, 8x4 micro, optional r-batch via grid.z ----------------
__global__ void __launch_bounds__(256) k_gemm(int K, int F, int Nout,
        const float* __restrict__ A, const float* __restrict__ Wt, size_t wStride,
        const float* __restrict__ bias, const float* __restrict__ resid,
        float* __restrict__ C, size_t cStride) {
    const float* W = Wt + blockIdx.z * wStride;
    float* Cp = C + blockIdx.z * cStride;
    __shared__ float As[16][128];
    __shared__ float Bs[16][68];
    int tid = threadIdx.x;
    int bm = blockIdx.x*128, bn = blockIdx.y*64;
    int tx = tid & 15, ty = tid >> 4;
    float acc[8][4] = {};
    int am = tid >> 1, akq = (tid & 1)*8;
    int bk = tid >> 4, bo = (tid & 15)*4;
    for (int k0 = 0; k0 < K; k0 += 16) {
        const float* Ar = A + ((size_t)(k0/F)*Nn + bm + am)*F + (k0 % F) + akq;
        float4 a0 = *(const float4*)Ar;
        float4 a1 = *(const float4*)(Ar + 4);
        As[akq+0][am]=a0.x; As[akq+1][am]=a0.y; As[akq+2][am]=a0.z; As[akq+3][am]=a0.w;
        As[akq+4][am]=a1.x; As[akq+5][am]=a1.y; As[akq+6][am]=a1.z; As[akq+7][am]=a1.w;
        *(float4*)&Bs[bk][bo] = *(const float4*)(W + (size_t)(k0 + bk)*Nout + bn + bo);
        __syncthreads();
        #pragma unroll
        for (int kk = 0; kk < 16; kk++) {
            float4 b  = *(float4*)&Bs[kk][tx*4];
            float4 xA = *(float4*)&As[kk][ty*8];
            float4 xB = *(float4*)&As[kk][ty*8+4];
            float af[8] = {xA.x,xA.y,xA.z,xA.w,xB.x,xB.y,xB.z,xB.w};
            #pragma unroll
            for (int i = 0; i < 8; i++) {
                acc[i][0] += af[i]*b.x; acc[i][1] += af[i]*b.y;
                acc[i][2] += af[i]*b.z; acc[i][3] += af[i]*b.w;
            }
        }
        __syncthreads();
    }
    #pragma unroll
    for (int i = 0; i < 8; i++) {
        int m = bm + ty*8 + i;
        float4 v = make_float4(acc[i][0], acc[i][1], acc[i][2], acc[i][3]);
        if (bias) {
            const float* bp = bias + bn + tx*4;
            v.x += bp[0]; v.y += bp[1]; v.z += bp[2]; v.w += bp[3];
        }
        if (resid) {
            const float* rp = resid + (size_t)m*Nout + bn + tx*4;
            v.x += rp[0]; v.y += rp[1]; v.z += rp[2]; v.w += rp[3];
        }
        *(float4*)(Cp + (size_t)m*Nout + bn + tx*4) = v;
    }
}

// ---------------- final sum over r + bias + residual (layer 3) ----------------
__global__ void k_sum3(const float* __restrict__ b3, const float* __restrict__ X,
                       float* __restrict__ out) {
    int i = blockIdx.x*256 + threadIdx.x;          // Nn*128/4 = 131072 float4s
    const float4* h = (const float4*)g_hn;
    float4 v = h[i];
    float4 v1 = h[131072 + i], v2 = h[262144 + i], v3 = h[393216 + i];
    float4 bb = ((const float4*)b3)[i & 31];
    float4 xx = ((const float4*)X)[i];
    v.x += v1.x + v2.x + v3.x + bb.x + xx.x;
    v.y += v1.y + v2.y + v3.y + bb.y + xx.y;
    v.z += v1.z + v2.z + v3.z + bb.z + xx.z;
    v.w += v1.w + v2.w + v3.w + bb.w + xx.w;
    ((float4*)out)[i] = v;
}

// ---------------- BN stats ----------------
__global__ void k_bnstat(const float* __restrict__ Xin) {
    int h = blockIdx.x;
    float s = 0.f, q = 0.f;
    for (int n = threadIdx.x; n < Nn; n += 256) {
        float v = Xin[(size_t)n*HDim + h];
        s += v; q += v*v;
    }
    __shared__ float sh[256], sh2[256];
    sh[threadIdx.x] = s; sh2[threadIdx.x] = q; __syncthreads();
    for (int st = 128; st; st >>= 1) {
        if (threadIdx.x < st) { sh[threadIdx.x] += sh[threadIdx.x+st]; sh2[threadIdx.x] += sh2[threadIdx.x+st]; }
        __syncthreads();
    }
    if (threadIdx.x == 0) {
        float mu = sh[0] / (float)Nn;
        float var = sh2[0] / (float)Nn - mu*mu;
        g_mu[h] = mu;
        g_rs[h] = rsqrtf(var + 1e-5f);
    }
}

// ---------------- BN + LN + ELU ----------------
__global__ void k_bnln(const float* __restrict__ Xin,
                       const float* __restrict__ bg, const float* __restrict__ bb,
                       const float* __restrict__ lg, const float* __restrict__ lb,
                       float* __restrict__ Out) {
    int n = blockIdx.x, h = threadIdx.x;
    float v = (Xin[(size_t)n*HDim + h] - g_mu[h]) * g_rs[h] * bg[h] + bb[h];
    __shared__ float sh[256], sh2[256];
    sh[h] = v; sh2[h] = v*v; __syncthreads();
    for (int st = 128; st; st >>= 1) {
        if (h < st) { sh[h] += sh[h+st]; sh2[h] += sh2[h+st]; }
        __syncthreads();
    }
    float m = sh[0] / (float)HDim;
    float var = sh2[0] / (float)HDim - m*m;
    float u = (v - m) * rsqrtf(var + 1e-5f) * lg[h] + lb[h];
    Out[(size_t)n*HDim + h] = (u > 0.f) ? u : expm1f(u);
}

// ---------------- launch ----------------
extern "C" void kernel_launch(void* const* d_in, const int* in_sizes, int n_in,
                              void* d_out, int out_size) {
    const float* X   = (const float*)d_in[0];
    const float* H   = (const float*)d_in[1];
    const float* W1  = (const float*)d_in[2];
    const float* W2  = (const float*)d_in[3];
    const float* W3  = (const float*)d_in[4];
    const float* imp = (const float*)d_in[5];
    const float* b1  = (const float*)d_in[6];
    const float* b2  = (const float*)d_in[7];
    const float* b3  = (const float*)d_in[8];
    const float* bng = (const float*)d_in[9];
    const float* bnb = (const float*)d_in[10];
    const float* lng = (const float*)d_in[11];
    const float* lnb = (const float*)d_in[12];
    const float* ra  = (const float*)d_in[13];
    float* out = (float*)d_out;

    void *pA, *pB, *pHn, *pWs, *pY;
    cudaGetSymbolAddress(&pA,  g_bufA);
    cudaGetSymbolAddress(&pB,  g_bufB);
    cudaGetSymbolAddress(&pHn, g_hn);
    cudaGetSymbolAddress(&pWs, g_ws);
    cudaGetSymbolAddress(&pY,  g_y);
    float* bufA = (float*)pA;
    float* bufB = (float*)pB;
    const float* hn = (const float*)pHn;
    const float* ws = (const float*)pWs;
    float* ybuf = (float*)pY;

    // --- structure extraction: one pass over H ---
    k_zero<<<32, 256>>>();
    k_prep<<<1, 32>>>(ra, imp);
    k_pass1<<<Rr*Nn/8, 256>>>(H);
    k_degE2<<<Rr*64, 256>>>();
    k_de<<<32, 256>>>();
    k_scanE<<<1, 1024>>>();
    k_scanN<<<1, 1024>>>();
    k_fillb<<<Rr*Nn, 256>>>();

    // --- conv1: F=128 -> 256 ---
    k_spmm_t<128><<<Rr*Ee, 128>>>(X, 0);
    k_spmm_n<128><<<Rr*Nn, 128>>>();
    k_ws<<<(Rr*128*256 + 255)/256, 256>>>(W1, 128*256, 0, Rr*128*256);
    k_gemm<<<dim3(Nn/128, 4, 1), 256>>>(Rr*128, 128, 256, hn, ws, 0, b1, nullptr, bufA, 0);
    k_bnstat<<<HDim, 256>>>(bufA);
    k_bnln<<<Nn, HDim>>>(bufA, bng, bnb, lng, lnb, bufB);

    // --- conv2: 256 -> 256 ---
    k_spmm_t<256><<<Rr*Ee, 128>>>(bufB, 0);
    k_spmm_n<256><<<Rr*Nn, 128>>>();
    k_ws<<<(Rr*256*256 + 255)/256, 256>>>(W2, 256*256, 1, Rr*256*256);
    k_gemm<<<dim3(Nn/128, 4, 1), 256>>>(Rr*256, 256, 256, hn, ws, 0, b2, nullptr, bufA, 0);
    k_bnstat<<<HDim, 256>>>(bufA);
    k_bnln<<<Nn, HDim>>>(bufA, bng + HDim, bnb + HDim, lng + HDim, lnb + HDim, bufB);

    // --- conv3 (reordered): Y_r = bufB @ (s_r*W3_r), then SpMMs at F=128, then sum_r ---
    k_ws<<<(Rr*256*128 + 255)/256, 256>>>(W3, 256*128, 2, Rr*256*128);
    k_gemm<<<dim3(Nn/128, 2, Rr), 256>>>(256, 256, 128, bufB, ws, (size_t)256*128,
                                         nullptr, nullptr, ybuf, (size_t)Nn*128);
    k_spmm_t<128><<<Rr*Ee, 128>>>(ybuf, Nn*128);
    k_spmm_n<128><<<Rr*Nn, 128>>>();
    k_sum3<<<512, 256>>>(b3, X, out);
}